// round 3
// baseline (speedup 1.0000x reference)
#include <cuda_runtime.h>
#include <cstdint>

#define BB 64
#define CC 4096
#define IND 512
#define OO 16
#define TI 16                 // i-tile
#define NTILES (IND / TI)     // 32
#define NCAP 2                // capsules per CTA
#define NTH 32                // one warp per CTA

// ---- packed f32x2 helpers ----
__device__ __forceinline__ uint64_t pack_dup(float x) {
    uint64_t r;
    asm("mov.b64 %0, {%1, %1};" : "=l"(r) : "f"(x));
    return r;
}
__device__ __forceinline__ void fma2(uint64_t& d, uint64_t a, uint64_t b) {
    asm("fma.rn.f32x2 %0, %1, %2, %0;" : "+l"(d) : "l"(a), "l"(b));
}
__device__ __forceinline__ void unpack2(uint64_t v, float& lo, float& hi) {
    asm("mov.b64 {%0, %1}, %2;" : "=f"(lo), "=f"(hi) : "l"(v));
}

// ---- cp.async 16B ----
__device__ __forceinline__ void cp16(void* dst_smem, const void* src) {
    uint32_t d = (uint32_t)__cvta_generic_to_shared(dst_smem);
    asm volatile("cp.async.ca.shared.global [%0], [%1], 16;"
                 :: "r"(d), "l"(src) : "memory");
}
__device__ __forceinline__ void cp_commit() {
    asm volatile("cp.async.commit_group;" ::: "memory");
}
__device__ __forceinline__ void cp_wait1() {
    asm volatile("cp.async.wait_group 1;" ::: "memory");
}
__device__ __forceinline__ void cp_wait0() {
    asm volatile("cp.async.wait_group 0;" ::: "memory");
}

// x rows padded: 16 floats data + 4 pad = 5 float4 per (cap,b) row.
// Bank-conflict-free: lanes read rows tb+8k; bank start (20*tb)%32 all distinct.
#define XROW 5

__global__ __launch_bounds__(NTH, 9)
void primarycaps_kernel(const float* __restrict__ x,
                        const float* __restrict__ W,
                        const float* __restrict__ bias,
                        float* __restrict__ out)
{
    __shared__ float4 sX[2][NCAP * BB * XROW];   // 2 x 10 KB
    __shared__ float4 sW[2][NCAP * TI * 4];      // 2 x 2 KB

    const int c0  = blockIdx.x * NCAP;
    const int t   = threadIdx.x;
    const int tb  = t & 7;           // b-group: owns b = tb + 8k
    const int to  = (t >> 3) & 1;    // o-half
    const int cap = t >> 4;          // capsule within CTA

    // ---- staging maps ----
    const int i4s = t & 3;           // x: 16B chunk within 64B i-tile row
    const int bbs = t >> 2;          // x: base b row (0..7)
    const int wch = t & 3;           // W: 16B chunk
    const int wi  = (t >> 2) & 7;    // W: base i row (0..7), +8*m

    const float* xg0 = x + ((size_t)bbs * CC + c0) * IND + i4s * 4;

    // ---- issue tile 0 ----
    {
        #pragma unroll
        for (int cc = 0; cc < NCAP; ++cc)
            #pragma unroll
            for (int k = 0; k < 8; ++k)
                cp16(&sX[0][(cc * BB + bbs + 8 * k) * XROW + i4s],
                     xg0 + (size_t)cc * IND + (size_t)(8 * k) * CC * IND);
        #pragma unroll
        for (int cc = 0; cc < NCAP; ++cc)
            #pragma unroll
            for (int m = 0; m < 2; ++m) {
                const int i = wi + 8 * m;
                cp16(&sW[0][(cc * TI + i) * 4 + wch],
                     W + ((size_t)(c0 + cc) * IND + i) * OO + wch * 4);
            }
        cp_commit();
    }

    // accumulators: 8 b-rows x 4 o-pairs (packed f32x2)
    uint64_t acc[8][4];
    #pragma unroll
    for (int k = 0; k < 8; ++k)
        #pragma unroll
        for (int j = 0; j < 4; ++j)
            acc[k][j] = 0ULL;

    for (int j = 0; j < NTILES; ++j) {
        // issue tile j+1 into the other buffer, then wait for tile j
        if (j + 1 < NTILES) {
            const int nb = (j + 1) & 1;
            const float* xg = xg0 + (size_t)(j + 1) * TI;
            #pragma unroll
            for (int cc = 0; cc < NCAP; ++cc)
                #pragma unroll
                for (int k = 0; k < 8; ++k)
                    cp16(&sX[nb][(cc * BB + bbs + 8 * k) * XROW + i4s],
                         xg + (size_t)cc * IND + (size_t)(8 * k) * CC * IND);
            const size_t wbase = (size_t)(j + 1) * TI;
            #pragma unroll
            for (int cc = 0; cc < NCAP; ++cc)
                #pragma unroll
                for (int m = 0; m < 2; ++m) {
                    const int i = wi + 8 * m;
                    cp16(&sW[nb][(cc * TI + i) * 4 + wch],
                         W + ((size_t)(c0 + cc) * IND + wbase + i) * OO + wch * 4);
                }
            cp_commit();
            cp_wait1();        // tile j landed; j+1 in flight
        } else {
            cp_wait0();
        }
        __syncwarp();

        // ---- compute tile j ----
        const float4* __restrict__ xb = sX[j & 1] + cap * (BB * XROW);
        const float4* __restrict__ wb = sW[j & 1] + cap * (TI * 4);

        #pragma unroll
        for (int q = 0; q < 4; ++q) {           // 4-i blocks
            float4 xv[8];
            #pragma unroll
            for (int k = 0; k < 8; ++k)
                xv[k] = xb[(tb + 8 * k) * XROW + q];   // conflict-free LDS.128

            #pragma unroll
            for (int r = 0; r < 4; ++r) {       // i within block
                const int i = q * 4 + r;
                // this lane's 8 o's = 2 LDS.128 (warp-broadcast per phase)
                const ulonglong2 wA =
                    *(const ulonglong2*)&wb[i * 4 + to * 2];
                const ulonglong2 wB =
                    *(const ulonglong2*)&wb[i * 4 + to * 2 + 1];

                #pragma unroll
                for (int k = 0; k < 8; ++k) {
                    const float xs = (r == 0) ? xv[k].x :
                                     (r == 1) ? xv[k].y :
                                     (r == 2) ? xv[k].z : xv[k].w;
                    const uint64_t xd = pack_dup(xs);
                    fma2(acc[k][0], xd, wA.x);
                    fma2(acc[k][1], xd, wA.y);
                    fma2(acc[k][2], xd, wB.x);
                    fma2(acc[k][3], xd, wB.y);
                }
            }
        }
        __syncwarp();   // everyone done reading buffer j before it's refilled
    }

    // ---- epilogue ----
    const int c  = c0 + cap;
    const int o0 = to * 8;
    const float4* bias4 = (const float4*)(bias + (size_t)c * OO + o0);
    const float4 bz0 = bias4[0];
    const float4 bz1 = bias4[1];

    #pragma unroll
    for (int k = 0; k < 8; ++k) {
        float v0, v1, v2, v3, v4, v5, v6, v7;
        unpack2(acc[k][0], v0, v1);
        unpack2(acc[k][1], v2, v3);
        unpack2(acc[k][2], v4, v5);
        unpack2(acc[k][3], v6, v7);

        float4 lo = make_float4(v0 + bz0.x, v1 + bz0.y, v2 + bz0.z, v3 + bz0.w);
        float4 hi = make_float4(v4 + bz1.x, v5 + bz1.y, v6 + bz1.z, v7 + bz1.w);

        const int b = tb + 8 * k;
        float* op = out + ((size_t)b * CC + c) * OO + o0;
        *(float4*)(op)     = lo;
        *(float4*)(op + 4) = hi;
    }
}

extern "C" void kernel_launch(void* const* d_in, const int* in_sizes, int n_in,
                              void* d_out, int out_size)
{
    (void)in_sizes; (void)n_in; (void)out_size;
    const float* x    = (const float*)d_in[0];
    const float* W    = (const float*)d_in[1];
    const float* bias = (const float*)d_in[2];
    float*       out  = (float*)d_out;

    primarycaps_kernel<<<CC / NCAP, NTH>>>(x, W, bias, out);
}